// round 6
// baseline (speedup 1.0000x reference)
#include <cuda_runtime.h>
#include <cuda_bf16.h>
#include <cstdint>
#include <math.h>

#define N_NODES 50000
#define N_EDGES 600000
#define D 128
#define BN_EPS 1e-5f

#define BM 64
#define LDSB 136                 // smem row stride in bf16 elements (272B, conflict-free)
#define GEMM_GRID 304
// smem: Ws_hi + Ws_lo (128*136*2B each) + As_hi + As_lo (64*136*2B each) + 2*128 floats
#define GEMM_SMEM ((2 * D * LDSB + 2 * BM * LDSB) * 2 + 2 * D * 4)

// ---------------- scratch (static device globals; no allocation) ----------------
__device__ float  g_agg[(size_t)N_NODES * D];   // x + sum(relu(x_src + e))
__device__ float  g_h1 [(size_t)N_NODES * D];
__device__ float  g_h2 [(size_t)N_NODES * D];
__device__ double g_sum[D];
__device__ double g_sumsq[D];
__device__ float  g_scale[D];
__device__ float  g_shift[D];
// CSR build
__device__ int g_cnt[N_NODES];
__device__ int g_ex [N_NODES];
__device__ int g_bsum[256];
__device__ int g_row[N_NODES + 1];
__device__ int g_cur[N_NODES];
__device__ int g_perm[N_EDGES];

// ---------------- K0: zero counters + BN accumulators ----------------
__global__ void zero_kernel() {
    int i = blockIdx.x * blockDim.x + threadIdx.x;
    if (i < N_NODES) g_cnt[i] = 0;
    if (blockIdx.x == 0 && threadIdx.x < D) {
        g_sum[threadIdx.x] = 0.0; g_sumsq[threadIdx.x] = 0.0;
    }
}

// ---------------- K1: histogram of dst ----------------
__global__ void hist_kernel(const int* __restrict__ edge_index) {
    int e = blockIdx.x * blockDim.x + threadIdx.x;
    if (e < N_EDGES) atomicAdd(&g_cnt[edge_index[N_EDGES + e]], 1);
}

// ---------------- K2a/b/c: exclusive scan of g_cnt -> g_row, g_cur ----------------
__device__ __forceinline__ int block_scan_excl(int v, int t, int* sh, int& total) {
    sh[t] = v; __syncthreads();
#pragma unroll
    for (int off = 1; off < 256; off <<= 1) {
        int y = (t >= off) ? sh[t - off] : 0;
        __syncthreads();
        sh[t] += y;
        __syncthreads();
    }
    total = sh[255];
    return sh[t] - v;
}

__global__ void scanA_kernel() {
    __shared__ int sh[256];
    int t = threadIdx.x;
    int i = blockIdx.x * 256 + t;
    int v = (i < N_NODES) ? g_cnt[i] : 0;
    int total;
    int ex = block_scan_excl(v, t, sh, total);
    if (i < N_NODES) g_ex[i] = ex;
    if (t == 0) g_bsum[blockIdx.x] = total;
}

__global__ void scanB_kernel(int nblocks) {
    __shared__ int sh[256];
    int t = threadIdx.x;
    int v = (t < nblocks) ? g_bsum[t] : 0;
    int total;
    int ex = block_scan_excl(v, t, sh, total);
    if (t < nblocks) g_bsum[t] = ex;
}

__global__ void scanC_kernel() {
    int t = threadIdx.x;
    int i = blockIdx.x * 256 + t;
    if (i < N_NODES) {
        int row = g_ex[i] + g_bsum[blockIdx.x];
        g_row[i] = row;
        g_cur[i] = row;
    }
    if (i == 0) g_row[N_NODES] = N_EDGES;
}

// ---------------- K3: fill permutation ----------------
__global__ void fill_kernel(const int* __restrict__ edge_index) {
    int e = blockIdx.x * blockDim.x + threadIdx.x;
    if (e < N_EDGES) {
        int slot = atomicAdd(&g_cur[edge_index[N_EDGES + e]], 1);
        g_perm[slot] = e;
    }
}

// ---------------- K4: gather-aggregate (one warp per node), agg = x + sum(msg) ----------------
__global__ void __launch_bounds__(256) agg_kernel(
    const float* __restrict__ x,
    const int*   __restrict__ edge_index,
    const float* __restrict__ edge_attr)
{
    int node = (blockIdx.x * blockDim.x + threadIdx.x) >> 5;
    int lane = threadIdx.x & 31;
    if (node >= N_NODES) return;
    int s = g_row[node], e = g_row[node + 1];

    float4 acc = *reinterpret_cast<const float4*>(&x[(size_t)node * D + lane * 4]);

    int eid = (s < e) ? g_perm[s] : 0;
    int src = (s < e) ? edge_index[eid] : 0;
    for (int p = s; p < e; p++) {
        int eid_n = 0, src_n = 0;
        if (p + 1 < e) eid_n = g_perm[p + 1];
        const float4 xs = *reinterpret_cast<const float4*>(&x[(size_t)src * D + lane * 4]);
        const float4 ea = *reinterpret_cast<const float4*>(&edge_attr[(size_t)eid * D + lane * 4]);
        if (p + 1 < e) src_n = edge_index[eid_n];
        acc.x += fmaxf(xs.x + ea.x, 0.f);
        acc.y += fmaxf(xs.y + ea.y, 0.f);
        acc.z += fmaxf(xs.z + ea.z, 0.f);
        acc.w += fmaxf(xs.w + ea.w, 0.f);
        eid = eid_n; src = src_n;
    }
    *reinterpret_cast<float4*>(&g_agg[(size_t)node * D + lane * 4]) = acc;
}

// ---------------- bf16 split helpers ----------------
__device__ __forceinline__ void split2(float v0, float v1, uint32_t& hw, uint32_t& lw) {
    __nv_bfloat16 h0 = __float2bfloat16_rn(v0);
    __nv_bfloat16 h1 = __float2bfloat16_rn(v1);
    __nv_bfloat16 l0 = __float2bfloat16_rn(v0 - __bfloat162float(h0));
    __nv_bfloat16 l1 = __float2bfloat16_rn(v1 - __bfloat162float(h1));
    hw = (uint32_t)__bfloat16_as_ushort(h0) | ((uint32_t)__bfloat16_as_ushort(h1) << 16);
    lw = (uint32_t)__bfloat16_as_ushort(l0) | ((uint32_t)__bfloat16_as_ushort(l1) << 16);
}

__device__ __forceinline__ void mma_bf16(float& c0, float& c1, float& c2, float& c3,
                                         uint32_t a0, uint32_t a1, uint32_t a2, uint32_t a3,
                                         uint32_t b0, uint32_t b1)
{
    asm("mma.sync.aligned.m16n8k16.row.col.f32.bf16.bf16.f32 "
        "{%0,%1,%2,%3}, {%4,%5,%6,%7}, {%8,%9}, {%0,%1,%2,%3};"
        : "+f"(c0), "+f"(c1), "+f"(c2), "+f"(c3)
        : "r"(a0), "r"(a1), "r"(a2), "r"(a3), "r"(b0), "r"(b1));
}

__device__ __forceinline__ uint32_t lds32(const uint16_t* p) {
    return *reinterpret_cast<const uint32_t*>(p);
}

// ---------------- K5/K6: bf16x3 tensor GEMM  out[i][j] = sum_k in[i][k] * W[j][k]
// Persistent CTAs; W split-staged once; A tile 64x128 with register prefetch pipeline.
// 8 warps 2(M)x4(N); warp tile 32x32 = 2 m-atoms x 4 n-atoms of m16n8k16; 3 MMAs/atom.
// LAYER 0: in = g_agg, out = relu(. + b1) -> g_h1
// LAYER 1: in = g_h1,  out = . + b2      -> g_h2, + BN column sums
template <int LAYER>
__global__ void __launch_bounds__(256, 2) gemm_mma_kernel(
    const float* __restrict__ W,
    const float* __restrict__ bias)
{
    extern __shared__ uint16_t sm16[];
    uint16_t* Ws_hi = sm16;
    uint16_t* Ws_lo = Ws_hi + D * LDSB;
    uint16_t* As_hi = Ws_lo + D * LDSB;
    uint16_t* As_lo = As_hi + BM * LDSB;
    float*    ColS  = reinterpret_cast<float*>(As_lo + BM * LDSB);
    float*    ColS2 = ColS + D;

    const float* __restrict__ A = (LAYER == 0) ? g_agg : g_h1;

    const int t    = threadIdx.x;
    const int lane = t & 31;
    const int warp = t >> 5;
    const int g    = lane >> 2;
    const int c    = lane & 3;
    const int wm   = warp >> 2;
    const int wn   = warp & 3;

    // stage W split into smem
    for (int p = t; p < D * D / 4; p += 256) {
        int j = p >> 5;
        int k = (p & 31) << 2;
        float4 w = *reinterpret_cast<const float4*>(&W[(size_t)j * D + k]);
        uint32_t h01, l01, h23, l23;
        split2(w.x, w.y, h01, l01);
        split2(w.z, w.w, h23, l23);
        uint16_t* ph = &Ws_hi[j * LDSB + k];
        uint16_t* pl = &Ws_lo[j * LDSB + k];
        *reinterpret_cast<uint32_t*>(ph)     = h01;
        *reinterpret_cast<uint32_t*>(ph + 2) = h23;
        *reinterpret_cast<uint32_t*>(pl)     = l01;
        *reinterpret_cast<uint32_t*>(pl + 2) = l23;
    }
    if (LAYER == 1 && t < D) { ColS[t] = 0.f; ColS2[t] = 0.f; }

    float bb0[4], bb1[4];
#pragma unroll
    for (int n = 0; n < 4; n++) {
        int col = wn * 32 + n * 8 + 2 * c;
        bb0[n] = bias[col];
        bb1[n] = bias[col + 1];
    }

    float bnS[8], bnS2[8];
    if (LAYER == 1) {
#pragma unroll
        for (int i = 0; i < 8; i++) { bnS[i] = 0.f; bnS2[i] = 0.f; }
    }

    // register prefetch buffer: 8 float4 per thread = one 64x128 tile
    float4 pre[8];
    int tile = blockIdx.x;
    if (tile * BM < N_NODES) {
#pragma unroll
        for (int q = 0; q < 8; q++) {
            int p = q * 256 + t;
            int gi = tile * BM + (p >> 5);
            pre[q] = (gi < N_NODES)
                ? *reinterpret_cast<const float4*>(&A[(size_t)gi * D + (p & 31) * 4])
                : make_float4(0.f, 0.f, 0.f, 0.f);
        }
    }

    for (; tile * BM < N_NODES; tile += gridDim.x) {
        const int rowBase = tile * BM;

        // ---- store prefetched tile to smem (split bf16) ----
#pragma unroll
        for (int q = 0; q < 8; q++) {
            int p = q * 256 + t;
            int r = p >> 5;
            int k = (p & 31) << 2;
            uint32_t h01, l01, h23, l23;
            split2(pre[q].x, pre[q].y, h01, l01);
            split2(pre[q].z, pre[q].w, h23, l23);
            uint16_t* ph = &As_hi[r * LDSB + k];
            uint16_t* pl = &As_lo[r * LDSB + k];
            *reinterpret_cast<uint32_t*>(ph)     = h01;
            *reinterpret_cast<uint32_t*>(ph + 2) = h23;
            *reinterpret_cast<uint32_t*>(pl)     = l01;
            *reinterpret_cast<uint32_t*>(pl + 2) = l23;
        }
        __syncthreads();

        // ---- issue prefetch of next tile (overlaps with MMA) ----
        int nt = tile + gridDim.x;
        if (nt * BM < N_NODES) {
#pragma unroll
            for (int q = 0; q < 8; q++) {
                int p = q * 256 + t;
                int gi = nt * BM + (p >> 5);
                pre[q] = (gi < N_NODES)
                    ? *reinterpret_cast<const float4*>(&A[(size_t)gi * D + (p & 31) * 4])
                    : make_float4(0.f, 0.f, 0.f, 0.f);
            }
        }

        float acc[2][4][4];
#pragma unroll
        for (int m = 0; m < 2; m++)
#pragma unroll
            for (int n = 0; n < 4; n++)
#pragma unroll
                for (int i = 0; i < 4; i++) acc[m][n][i] = 0.f;

#pragma unroll
        for (int kc = 0; kc < 8; kc++) {
            const int k0 = kc * 16;
            uint32_t ah[2][4], al[2][4];
#pragma unroll
            for (int m = 0; m < 2; m++) {
                const int r0 = (wm * 32 + m * 16 + g) * LDSB + k0 + 2 * c;
                const int r1 = r0 + 8 * LDSB;
                ah[m][0] = lds32(&As_hi[r0]);
                ah[m][1] = lds32(&As_hi[r1]);
                ah[m][2] = lds32(&As_hi[r0 + 8]);
                ah[m][3] = lds32(&As_hi[r1 + 8]);
                al[m][0] = lds32(&As_lo[r0]);
                al[m][1] = lds32(&As_lo[r1]);
                al[m][2] = lds32(&As_lo[r0 + 8]);
                al[m][3] = lds32(&As_lo[r1 + 8]);
            }
#pragma unroll
            for (int n = 0; n < 4; n++) {
                const int jb = (wn * 32 + n * 8 + g) * LDSB + k0 + 2 * c;
                uint32_t bh0 = lds32(&Ws_hi[jb]);
                uint32_t bh1 = lds32(&Ws_hi[jb + 8]);
                uint32_t bl0 = lds32(&Ws_lo[jb]);
                uint32_t bl1 = lds32(&Ws_lo[jb + 8]);
#pragma unroll
                for (int m = 0; m < 2; m++) {
                    mma_bf16(acc[m][n][0], acc[m][n][1], acc[m][n][2], acc[m][n][3],
                             al[m][0], al[m][1], al[m][2], al[m][3], bh0, bh1);
                    mma_bf16(acc[m][n][0], acc[m][n][1], acc[m][n][2], acc[m][n][3],
                             ah[m][0], ah[m][1], ah[m][2], ah[m][3], bl0, bl1);
                    mma_bf16(acc[m][n][0], acc[m][n][1], acc[m][n][2], acc[m][n][3],
                             ah[m][0], ah[m][1], ah[m][2], ah[m][3], bh0, bh1);
                }
            }
        }

        // ---- epilogue ----
#pragma unroll
        for (int m = 0; m < 2; m++) {
            const int r0 = rowBase + wm * 32 + m * 16 + g;
            const int r1 = r0 + 8;
#pragma unroll
            for (int n = 0; n < 4; n++) {
                const int col = wn * 32 + n * 8 + 2 * c;
                float v00 = acc[m][n][0] + bb0[n];
                float v01 = acc[m][n][1] + bb1[n];
                float v10 = acc[m][n][2] + bb0[n];
                float v11 = acc[m][n][3] + bb1[n];
                if (LAYER == 0) {
                    if (r0 < N_NODES)
                        *reinterpret_cast<float2*>(&g_h1[(size_t)r0 * D + col]) =
                            make_float2(fmaxf(v00, 0.f), fmaxf(v01, 0.f));
                    if (r1 < N_NODES)
                        *reinterpret_cast<float2*>(&g_h1[(size_t)r1 * D + col]) =
                            make_float2(fmaxf(v10, 0.f), fmaxf(v11, 0.f));
                } else {
                    if (r0 < N_NODES) {
                        *reinterpret_cast<float2*>(&g_h2[(size_t)r0 * D + col]) =
                            make_float2(v00, v01);
                        bnS [n * 2]     += v00;  bnS2[n * 2]     += v00 * v00;
                        bnS [n * 2 + 1] += v01;  bnS2[n * 2 + 1] += v01 * v01;
                    }
                    if (r1 < N_NODES) {
                        *reinterpret_cast<float2*>(&g_h2[(size_t)r1 * D + col]) =
                            make_float2(v10, v11);
                        bnS [n * 2]     += v10;  bnS2[n * 2]     += v10 * v10;
                        bnS [n * 2 + 1] += v11;  bnS2[n * 2 + 1] += v11 * v11;
                    }
                }
            }
        }
        __syncthreads();
    }

    if (LAYER == 1) {
#pragma unroll
        for (int n = 0; n < 4; n++) {
            const int col = wn * 32 + n * 8 + 2 * c;
            atomicAdd(&ColS [col],     bnS [n * 2]);
            atomicAdd(&ColS [col + 1], bnS [n * 2 + 1]);
            atomicAdd(&ColS2[col],     bnS2[n * 2]);
            atomicAdd(&ColS2[col + 1], bnS2[n * 2 + 1]);
        }
        __syncthreads();
        if (t < D) {
            atomicAdd(&g_sum[t],   (double)ColS[t]);
            atomicAdd(&g_sumsq[t], (double)ColS2[t]);
        }
    }
}

// ---------------- K7: BN finalize ----------------
__global__ void bn_finalize_kernel(const float* __restrict__ bn_w,
                                   const float* __restrict__ bn_b)
{
    int j = threadIdx.x;
    if (j >= D) return;
    double mean = g_sum[j] / (double)N_NODES;
    double var  = g_sumsq[j] / (double)N_NODES - mean * mean;
    if (var < 0.0) var = 0.0;
    float scale = bn_w[j] * rsqrtf((float)var + BN_EPS);
    g_scale[j] = scale;
    g_shift[j] = bn_b[j] - (float)mean * scale;
}

// ---------------- K8: BN apply + final ReLU -> d_out ----------------
__global__ void __launch_bounds__(256) apply_kernel(float* __restrict__ out)
{
    size_t p = (size_t)blockIdx.x * blockDim.x + threadIdx.x;
    size_t tot4 = (size_t)N_NODES * D / 4;
    if (p >= tot4) return;
    size_t e = p * 4;
    int col = (int)(e & (D - 1));
    float4 v = reinterpret_cast<const float4*>(g_h2)[p];
    float4 o;
    o.x = fmaxf(v.x * g_scale[col + 0] + g_shift[col + 0], 0.f);
    o.y = fmaxf(v.y * g_scale[col + 1] + g_shift[col + 1], 0.f);
    o.z = fmaxf(v.z * g_scale[col + 2] + g_shift[col + 2], 0.f);
    o.w = fmaxf(v.w * g_scale[col + 3] + g_shift[col + 3], 0.f);
    reinterpret_cast<float4*>(out)[p] = o;
}

// ---------------- launcher ----------------
extern "C" void kernel_launch(void* const* d_in, const int* in_sizes, int n_in,
                              void* d_out, int out_size)
{
    const float* x         = (const float*)d_in[0];
    const int*   edge_idx  = (const int*)  d_in[1];
    const float* edge_attr = (const float*)d_in[2];
    const float* w1        = (const float*)d_in[3];
    const float* b1        = (const float*)d_in[4];
    const float* w2        = (const float*)d_in[5];
    const float* b2        = (const float*)d_in[6];
    const float* bn_w      = (const float*)d_in[7];
    const float* bn_b      = (const float*)d_in[8];
    float* out = (float*)d_out;

    cudaFuncSetAttribute(gemm_mma_kernel<0>,
                         cudaFuncAttributeMaxDynamicSharedMemorySize, GEMM_SMEM);
    cudaFuncSetAttribute(gemm_mma_kernel<1>,
                         cudaFuncAttributeMaxDynamicSharedMemorySize, GEMM_SMEM);

    const int node_blocks = (N_NODES + 255) / 256;      // 196
    const int edge_blocks = (N_EDGES + 255) / 256;      // 2344

    zero_kernel <<<node_blocks, 256>>>();
    hist_kernel <<<edge_blocks, 256>>>(edge_idx);
    scanA_kernel<<<node_blocks, 256>>>();
    scanB_kernel<<<1, 256>>>(node_blocks);
    scanC_kernel<<<node_blocks, 256>>>();
    fill_kernel <<<edge_blocks, 256>>>(edge_idx);

    agg_kernel<<<(N_NODES * 32 + 255) / 256, 256>>>(x, edge_idx, edge_attr);

    gemm_mma_kernel<0><<<GEMM_GRID, 256, GEMM_SMEM>>>(w1, b1);
    gemm_mma_kernel<1><<<GEMM_GRID, 256, GEMM_SMEM>>>(w2, b2);

    bn_finalize_kernel<<<1, 128>>>(bn_w, bn_b);

    size_t tot4 = (size_t)N_NODES * D / 4;
    apply_kernel<<<(int)((tot4 + 255) / 256), 256>>>(out);
}